// round 7
// baseline (speedup 1.0000x reference)
#include <cuda_runtime.h>
#include <cuda_bf16.h>
#include <math.h>
#include <stdint.h>

#define T_SEQ   2048
#define D_MODEL 4096
#define NHEADS  32
#define KVHEADS 8
#define HDIM    128
#define WINDOW  1024
#define NPROJ   6144   // 4096 Q + 1024 K + 1024 V

// ---------------- scratch (device globals) ----------------
__device__ __nv_bfloat16 g_Ah[T_SEQ * D_MODEL];          // A planes: X, later Enc
__device__ __nv_bfloat16 g_Al[T_SEQ * D_MODEL];
__device__ __nv_bfloat16 g_Bph[D_MODEL * NPROJ];         // packed QKV proj weights (D, 6144)
__device__ __nv_bfloat16 g_Bpl[D_MODEL * NPROJ];
__device__ __nv_bfloat16 g_Boh[D_MODEL * D_MODEL];       // out proj (N*H, D)
__device__ __nv_bfloat16 g_Bol[D_MODEL * D_MODEL];
__device__ float g_QKV[T_SEQ * NPROJ];
// attention operand planes
__device__ __nv_bfloat16 g_Qh[T_SEQ * NHEADS * HDIM];
__device__ __nv_bfloat16 g_Ql2[T_SEQ * NHEADS * HDIM];
__device__ __nv_bfloat16 g_Kh[T_SEQ * KVHEADS * HDIM];
__device__ __nv_bfloat16 g_Kl[T_SEQ * KVHEADS * HDIM];
__device__ __nv_bfloat16 g_Vh[T_SEQ * KVHEADS * HDIM];
__device__ __nv_bfloat16 g_Vl[T_SEQ * KVHEADS * HDIM];

// ---------------- helpers ----------------
__device__ __forceinline__ void split_bf16(float v, __nv_bfloat16& hi, __nv_bfloat16& lo) {
    hi = __float2bfloat16(v);
    lo = __float2bfloat16(v - __bfloat162float(hi));
}
__device__ __forceinline__ void cp16(void* dst, const void* src) {
    uint32_t d = (uint32_t)__cvta_generic_to_shared(dst);
    asm volatile("cp.async.cg.shared.global [%0], [%1], 16;\n" :: "r"(d), "l"(src));
}
__device__ __forceinline__ void cp_commit() { asm volatile("cp.async.commit_group;\n"); }

__device__ __forceinline__ void ldsm4(uint32_t& r0, uint32_t& r1, uint32_t& r2, uint32_t& r3,
                                      const __nv_bfloat16* p) {
    uint32_t a = (uint32_t)__cvta_generic_to_shared(p);
    asm volatile("ldmatrix.sync.aligned.m8n8.x4.shared.b16 {%0,%1,%2,%3}, [%4];"
                 : "=r"(r0), "=r"(r1), "=r"(r2), "=r"(r3) : "r"(a));
}
__device__ __forceinline__ void ldsm4t(uint32_t& r0, uint32_t& r1, uint32_t& r2, uint32_t& r3,
                                       const __nv_bfloat16* p) {
    uint32_t a = (uint32_t)__cvta_generic_to_shared(p);
    asm volatile("ldmatrix.sync.aligned.m8n8.x4.trans.shared.b16 {%0,%1,%2,%3}, [%4];"
                 : "=r"(r0), "=r"(r1), "=r"(r2), "=r"(r3) : "r"(a));
}
__device__ __forceinline__ void mma16816(float* c, const uint32_t* a, uint32_t b0, uint32_t b1) {
    asm volatile(
        "mma.sync.aligned.m16n8k16.row.col.f32.bf16.bf16.f32 "
        "{%0,%1,%2,%3}, {%4,%5,%6,%7}, {%8,%9}, {%0,%1,%2,%3};"
        : "+f"(c[0]), "+f"(c[1]), "+f"(c[2]), "+f"(c[3])
        : "r"(a[0]), "r"(a[1]), "r"(a[2]), "r"(a[3]), "r"(b0), "r"(b1));
}
__device__ __forceinline__ void pack_split(float a, float b, uint32_t& hi, uint32_t& lo) {
    __nv_bfloat16 ha = __float2bfloat16(a);
    __nv_bfloat16 hb = __float2bfloat16(b);
    float ra = a - __bfloat162float(ha);
    float rb = b - __bfloat162float(hb);
    __nv_bfloat162 h2 = __halves2bfloat162(ha, hb);
    __nv_bfloat162 l2 = __halves2bfloat162(__float2bfloat16(ra), __float2bfloat16(rb));
    hi = *reinterpret_cast<uint32_t*>(&h2);
    lo = *reinterpret_cast<uint32_t*>(&l2);
}

// ---------------- pack + convert all weights / X (division-free) ----------------
__global__ void pack_convert(const float* __restrict__ x, const float* __restrict__ qw,
                             const float* __restrict__ kvw, const float* __restrict__ ow) {
    const int stride = gridDim.x * blockDim.x;
    const int tid = blockIdx.x * blockDim.x + threadIdx.x;

    const int NX = T_SEQ * D_MODEL;
    for (int i = tid; i < NX; i += stride) split_bf16(x[i], g_Ah[i], g_Al[i]);

    for (int d = blockIdx.x; d < D_MODEL; d += gridDim.x) {
        for (int col = threadIdx.x; col < NPROJ; col += blockDim.x) {
            int h = col & 127;
            float w;
            if (col < 4096) {
                int nn = col >> 7;
                w = qw[(((size_t)nn * D_MODEL + d) << 7) + h];
            } else if (col < 5120) {
                int k = (col - 4096) >> 7;
                w = kvw[(((size_t)k * D_MODEL + d) << 7) + h];
            } else {
                int k = (col - 5120) >> 7;
                w = kvw[(((size_t)(KVHEADS + k) * D_MODEL + d) << 7) + h];
            }
            size_t i = (size_t)d * NPROJ + col;
            split_bf16(w, g_Bph[i], g_Bpl[i]);
        }
    }

    const int NO = D_MODEL * D_MODEL;
    for (int i = tid; i < NO; i += stride) split_bf16(ow[i], g_Boh[i], g_Bol[i]);
}

// ---------------- bf16-split tensor-core GEMM: 512 threads, 3-stage, 1 sync/chunk ----------------
#define KC 64
#define SA 72
#define SB 136
#define OFF_AL (128 * SA)
#define OFF_BH (2 * 128 * SA)
#define OFF_BL (2 * 128 * SA + KC * SB)
#define STAGE_ELEMS (2 * 128 * SA + 2 * KC * SB)   // 35840 elems = 71680 B ; 3 stages = 215040 B

__global__ __launch_bounds__(512)
void gemm_bf16split(const __nv_bfloat16* __restrict__ Ahg, const __nv_bfloat16* __restrict__ Alg,
                    const __nv_bfloat16* __restrict__ Bhg, const __nv_bfloat16* __restrict__ Blg,
                    float* __restrict__ C, int M, int Nc, int Kd) {
    extern __shared__ __nv_bfloat16 smem[];
    const int tid  = threadIdx.x;
    const int lane = tid & 31;
    const int wid  = tid >> 5;
    const int wm   = wid >> 2;     // 0..3
    const int wn   = wid & 3;      // 0..3
    const int row0 = blockIdx.y * 128;
    const int n0   = blockIdx.x * 128;
    const int lrow = lane & 15;
    const int lcol = (lane >> 4) << 3;

    float acc[2][4][4];
    #pragma unroll
    for (int mt = 0; mt < 2; mt++)
        #pragma unroll
        for (int nt = 0; nt < 4; nt++)
            #pragma unroll
            for (int r = 0; r < 4; r++) acc[mt][nt][r] = 0.f;

    const int KT = Kd >> 6;

    auto stage_copy = [&](int buf, int k0) {
        __nv_bfloat16* s = smem + buf * STAGE_ELEMS;
        #pragma unroll
        for (int c = tid; c < 1024; c += 512) {
            int r = c >> 3, col = (c & 7) << 3;
            size_t g = (size_t)(row0 + r) * Kd + k0 + col;
            cp16(s + r * SA + col, Ahg + g);
            cp16(s + OFF_AL + r * SA + col, Alg + g);
        }
        #pragma unroll
        for (int c = tid; c < 1024; c += 512) {
            int r = c >> 4, col = (c & 15) << 3;
            size_t g = (size_t)(k0 + r) * Nc + n0 + col;
            cp16(s + OFF_BH + r * SB + col, Bhg + g);
            cp16(s + OFF_BL + r * SB + col, Blg + g);
        }
    };

    stage_copy(0, 0); cp_commit();
    stage_copy(1, 64); cp_commit();

    int stage = 0;
    for (int kt = 0; kt < KT; kt++) {
        if (kt < KT - 1) asm volatile("cp.async.wait_group 1;\n");
        else             asm volatile("cp.async.wait_group 0;\n");
        __syncthreads();
        // prefetch chunk kt+2 into the buffer consumed at kt-1 (safe: all warps passed barrier)
        if (kt + 2 < KT) {
            int nb = stage + 2; if (nb >= 3) nb -= 3;
            stage_copy(nb, (kt + 2) << 6);
            cp_commit();
        }

        const __nv_bfloat16* s  = smem + stage * STAGE_ELEMS;
        const __nv_bfloat16* Ah = s;
        const __nv_bfloat16* Al = s + OFF_AL;
        const __nv_bfloat16* Bh = s + OFF_BH;
        const __nv_bfloat16* Bl = s + OFF_BL;

        #pragma unroll
        for (int k16 = 0; k16 < 4; k16++) {
            const int kc = k16 << 4;
            uint32_t ah[2][4], al[2][4];
            #pragma unroll
            for (int mt = 0; mt < 2; mt++) {
                const __nv_bfloat16* pa = Ah + (wm * 32 + mt * 16 + lrow) * SA + kc + lcol;
                ldsm4(ah[mt][0], ah[mt][1], ah[mt][2], ah[mt][3], pa);
                const __nv_bfloat16* pl = Al + (wm * 32 + mt * 16 + lrow) * SA + kc + lcol;
                ldsm4(al[mt][0], al[mt][1], al[mt][2], al[mt][3], pl);
            }
            #pragma unroll
            for (int nt = 0; nt < 2; nt++) {
                uint32_t bh[4], bl[4];
                const __nv_bfloat16* pb = Bh + (kc + lrow) * SB + wn * 32 + nt * 16 + lcol;
                ldsm4t(bh[0], bh[1], bh[2], bh[3], pb);
                const __nv_bfloat16* pbl = Bl + (kc + lrow) * SB + wn * 32 + nt * 16 + lcol;
                ldsm4t(bl[0], bl[1], bl[2], bl[3], pbl);
                #pragma unroll
                for (int mt = 0; mt < 2; mt++) {
                    mma16816(acc[mt][2 * nt],     ah[mt], bh[0], bh[1]);
                    mma16816(acc[mt][2 * nt],     ah[mt], bl[0], bl[1]);
                    mma16816(acc[mt][2 * nt],     al[mt], bh[0], bh[1]);
                    mma16816(acc[mt][2 * nt + 1], ah[mt], bh[2], bh[3]);
                    mma16816(acc[mt][2 * nt + 1], ah[mt], bl[2], bl[3]);
                    mma16816(acc[mt][2 * nt + 1], al[mt], bh[2], bh[3]);
                }
            }
        }
        stage++; if (stage == 3) stage = 0;
    }

    float* Cb = C + (size_t)(row0 + wm * 32) * Nc + n0 + wn * 32;
    const int g  = lane >> 2;
    const int tc = (lane & 3) * 2;
    #pragma unroll
    for (int mt = 0; mt < 2; mt++)
        #pragma unroll
        for (int nt = 0; nt < 4; nt++) {
            float2 v0 = make_float2(acc[mt][nt][0], acc[mt][nt][1]);
            float2 v1 = make_float2(acc[mt][nt][2], acc[mt][nt][3]);
            *reinterpret_cast<float2*>(Cb + (size_t)(mt * 16 + g) * Nc + nt * 8 + tc)     = v0;
            *reinterpret_cast<float2*>(Cb + (size_t)(mt * 16 + g + 8) * Nc + nt * 8 + tc) = v1;
        }
}

// ---------------- fused RoPE + scale + bf16 hi/lo split ----------------
__global__ void rope_split(const float* __restrict__ src, int srcStride, int srcOff,
                           const int* __restrict__ pos, int n_heads, float scale,
                           __nv_bfloat16* __restrict__ dh, __nv_bfloat16* __restrict__ dl) {
    int idx = blockIdx.x * blockDim.x + threadIdx.x;
    int total = T_SEQ * n_heads * 64;
    if (idx >= total) return;
    int hh = idx & 63;
    int nh = (idx >> 6) % n_heads;
    int t  = idx / (n_heads << 6);
    float ts  = powf(10000.0f, (float)hh * (1.0f / 64.0f));
    float ang = (float)pos[t] / ts;
    float sv = sinf(ang), cv = cosf(ang);
    size_t sbase = (size_t)t * srcStride + srcOff + nh * HDIM;
    size_t dbase = (size_t)t * (n_heads * HDIM) + nh * HDIM;
    float a = src[sbase + hh], b = src[sbase + hh + 64];
    float o1 = (a * cv - b * sv) * scale;
    float o2 = (b * cv + a * sv) * scale;
    split_bf16(o1, dh[dbase + hh], dl[dbase + hh]);
    split_bf16(o2, dh[dbase + hh + 64], dl[dbase + hh + 64]);
}

__global__ void v_split() {
    int stride = gridDim.x * blockDim.x;
    int tid = blockIdx.x * blockDim.x + threadIdx.x;
    const int N = T_SEQ * KVHEADS * HDIM;
    for (int i = tid; i < N; i += stride) {
        int t = i >> 10, c = i & 1023;
        split_bf16(g_QKV[(size_t)t * NPROJ + 5120 + c], g_Vh[i], g_Vl[i]);
    }
}

// ---------------- tensor-core flash attention (unchanged from R5) ----------------
#define AST 136
#define PLANE (64 * AST)
#define STAGE4 (4 * PLANE)

__global__ __launch_bounds__(256, 1)
void attn_tc(const int* __restrict__ segpos) {
    extern __shared__ __nv_bfloat16 dsm[];
    __shared__ int sp[128];
    __shared__ int s_pmin, s_pmax;

    const int n   = blockIdx.x;
    const int t0  = blockIdx.y * 128;
    const int kvh = n >> 2;
    const int tid = threadIdx.x;
    const int lane = tid & 31;
    const int w = tid >> 5;
    const int g8 = lane >> 2;
    const int q2 = (lane & 3) << 1;

    if (tid < 128) sp[tid] = segpos[t0 + tid];
    __syncthreads();
    if (tid == 0) {
        int mn = sp[0], mx = sp[0];
        for (int i = 1; i < 128; i++) { int v = sp[i]; mn = min(mn, v); mx = max(mx, v); }
        s_pmin = mn; s_pmax = mx;
    }
    __syncthreads();

    const int row0 = t0 + w * 16 + g8;
    uint32_t qh[8][4], ql[8][4];
    {
        const __nv_bfloat16* qb  = g_Qh  + (size_t)row0 * D_MODEL + n * HDIM;
        const __nv_bfloat16* qb8 = qb + (size_t)8 * D_MODEL;
        const __nv_bfloat16* lb  = g_Ql2 + (size_t)row0 * D_MODEL + n * HDIM;
        const __nv_bfloat16* lb8 = lb + (size_t)8 * D_MODEL;
        #pragma unroll
        for (int k16 = 0; k16 < 8; k16++) {
            int c0 = k16 * 16 + q2;
            qh[k16][0] = *reinterpret_cast<const uint32_t*>(qb  + c0);
            qh[k16][1] = *reinterpret_cast<const uint32_t*>(qb8 + c0);
            qh[k16][2] = *reinterpret_cast<const uint32_t*>(qb  + c0 + 8);
            qh[k16][3] = *reinterpret_cast<const uint32_t*>(qb8 + c0 + 8);
            ql[k16][0] = *reinterpret_cast<const uint32_t*>(lb  + c0);
            ql[k16][1] = *reinterpret_cast<const uint32_t*>(lb8 + c0);
            ql[k16][2] = *reinterpret_cast<const uint32_t*>(lb  + c0 + 8);
            ql[k16][3] = *reinterpret_cast<const uint32_t*>(lb8 + c0 + 8);
        }
    }

    float m[2]    = {-1e30f, -1e30f};
    float lsum[2] = {0.f, 0.f};
    float O[16][4];
    #pragma unroll
    for (int i = 0; i < 16; i++)
        #pragma unroll
        for (int j = 0; j < 4; j++) O[i][j] = 0.f;

    int s_lo = s_pmin - (WINDOW - 1); if (s_lo < 0) s_lo = 0;
    const int sb = s_lo & ~63;
    const int nIter = ((t0 + 127 - sb) >> 6) + 1;

    auto loadKV = [&](int stage, int s0) {
        __nv_bfloat16* base = dsm + stage * STAGE4;
        #pragma unroll
        for (int i = tid; i < 1024; i += 256) {
            int r = i >> 4, c = (i & 15) << 3;
            size_t g = (size_t)(s0 + r) * (KVHEADS * HDIM) + kvh * HDIM + c;
            cp16(base + r * AST + c,             g_Kh + g);
            cp16(base + PLANE + r * AST + c,     g_Kl + g);
            cp16(base + 2 * PLANE + r * AST + c, g_Vh + g);
            cp16(base + 3 * PLANE + r * AST + c, g_Vl + g);
        }
    };

    loadKV(0, sb); cp_commit();
    if (nIter > 1) { loadKV(1, sb + 64); cp_commit(); }

    const int krow = (lane & 7) + ((lane & 16) ? 8 : 0);
    const int ksel = (lane & 8) ? 8 : 0;
    const int vkey = lane & 15;
    const int vsel = (lane & 16) ? 8 : 0;

    for (int it = 0; it < nIter; it++) {
        const int s0 = sb + (it << 6);
        if (it + 1 < nIter) asm volatile("cp.async.wait_group 1;\n");
        else                asm volatile("cp.async.wait_group 0;\n");
        __syncthreads();

        const __nv_bfloat16* base = dsm + (it & 1) * STAGE4;
        const __nv_bfloat16* Kh = base;
        const __nv_bfloat16* Kl = base + PLANE;
        const __nv_bfloat16* Vh = base + 2 * PLANE;
        const __nv_bfloat16* Vl = base + 3 * PLANE;

        float S[8][4];
        #pragma unroll
        for (int i = 0; i < 8; i++)
            #pragma unroll
            for (int j = 0; j < 4; j++) S[i][j] = 0.f;

        #pragma unroll
        for (int k16 = 0; k16 < 8; k16++) {
            #pragma unroll
            for (int nt = 0; nt < 4; nt++) {
                uint32_t bh[4], bl[4];
                int koff = (nt * 16 + krow) * AST + k16 * 16 + ksel;
                ldsm4(bh[0], bh[1], bh[2], bh[3], Kh + koff);
                ldsm4(bl[0], bl[1], bl[2], bl[3], Kl + koff);
                mma16816(S[2 * nt],     qh[k16], bh[0], bh[1]);
                mma16816(S[2 * nt],     qh[k16], bl[0], bl[1]);
                mma16816(S[2 * nt],     ql[k16], bh[0], bh[1]);
                mma16816(S[2 * nt + 1], qh[k16], bh[2], bh[3]);
                mma16816(S[2 * nt + 1], qh[k16], bl[2], bl[3]);
                mma16816(S[2 * nt + 1], ql[k16], bh[2], bh[3]);
            }
        }

        const bool interior = (s0 + 63 <= t0) && (s0 > s_pmax - WINDOW) && (s0 + 63 < s_pmin + WINDOW);
        if (interior) {
            #pragma unroll
            for (int nt = 0; nt < 8; nt++)
                #pragma unroll
                for (int jj = 0; jj < 4; jj++) {
                    float e = __expf(S[nt][jj] * 0.04f);
                    S[nt][jj] = 50.f - __fdividef(100.f, e + 1.f);
                }
        } else {
            const int sp_r0 = sp[w * 16 + g8];
            const int sp_r1 = sp[w * 16 + g8 + 8];
            #pragma unroll
            for (int nt = 0; nt < 8; nt++) {
                int scol0 = s0 + nt * 8 + q2;
                #pragma unroll
                for (int jj = 0; jj < 4; jj++) {
                    int s = scol0 + (jj & 1);
                    int t = row0 + ((jj & 2) ? 8 : 0);
                    int p = (jj & 2) ? sp_r1 : sp_r0;
                    float e = __expf(S[nt][jj] * 0.04f);
                    float c = 50.f - __fdividef(100.f, e + 1.f);
                    bool ok = (s <= t) && (s > p - WINDOW) && (s < p + WINDOW);
                    S[nt][jj] = ok ? c : -1e30f;
                }
            }
        }

        #pragma unroll
        for (int h = 0; h < 2; h++) {
            float mx = -1e30f;
            #pragma unroll
            for (int nt = 0; nt < 8; nt++)
                mx = fmaxf(mx, fmaxf(S[nt][2 * h], S[nt][2 * h + 1]));
            mx = fmaxf(mx, __shfl_xor_sync(0xffffffffu, mx, 1));
            mx = fmaxf(mx, __shfl_xor_sync(0xffffffffu, mx, 2));
            float mnew  = fmaxf(m[h], mx);
            float alpha = __expf(m[h] - mnew);
            float rs = 0.f;
            #pragma unroll
            for (int nt = 0; nt < 8; nt++) {
                #pragma unroll
                for (int e2 = 0; e2 < 2; e2++) {
                    float sv = S[nt][2 * h + e2];
                    float pv = (sv < -9e29f) ? 0.f : __expf(sv - mnew);
                    S[nt][2 * h + e2] = pv;
                    rs += pv;
                }
            }
            rs += __shfl_xor_sync(0xffffffffu, rs, 1);
            rs += __shfl_xor_sync(0xffffffffu, rs, 2);
            lsum[h] = lsum[h] * alpha + rs;
            #pragma unroll
            for (int nt = 0; nt < 16; nt++) {
                O[nt][2 * h]     *= alpha;
                O[nt][2 * h + 1] *= alpha;
            }
            m[h] = mnew;
        }

        #pragma unroll
        for (int kt = 0; kt < 4; kt++) {
            uint32_t pah[4], pal[4];
            pack_split(S[2 * kt][0],     S[2 * kt][1],     pah[0], pal[0]);
            pack_split(S[2 * kt][2],     S[2 * kt][3],     pah[1], pal[1]);
            pack_split(S[2 * kt + 1][0], S[2 * kt + 1][1], pah[2], pal[2]);
            pack_split(S[2 * kt + 1][2], S[2 * kt + 1][3], pah[3], pal[3]);
            #pragma unroll
            for (int ht = 0; ht < 8; ht++) {
                uint32_t vh[4], vl[4];
                int voff = (kt * 16 + vkey) * AST + ht * 16 + vsel;
                ldsm4t(vh[0], vh[1], vh[2], vh[3], Vh + voff);
                ldsm4t(vl[0], vl[1], vl[2], vl[3], Vl + voff);
                mma16816(O[2 * ht],     pah, vh[0], vh[1]);
                mma16816(O[2 * ht],     pah, vl[0], vl[1]);
                mma16816(O[2 * ht],     pal, vh[0], vh[1]);
                mma16816(O[2 * ht + 1], pah, vh[2], vh[3]);
                mma16816(O[2 * ht + 1], pah, vl[2], vl[3]);
                mma16816(O[2 * ht + 1], pal, vh[2], vh[3]);
            }
        }
        __syncthreads();
        if (it + 2 < nIter) { loadKV(it & 1, s0 + 128); cp_commit(); }
    }

    #pragma unroll
    for (int h = 0; h < 2; h++) {
        float inv = 1.0f / lsum[h];
        int row = row0 + 8 * h;
        size_t dbase = (size_t)row * D_MODEL + n * HDIM + q2;
        #pragma unroll
        for (int nt = 0; nt < 16; nt++) {
            uint32_t hi, lo;
            pack_split(O[nt][2 * h] * inv, O[nt][2 * h + 1] * inv, hi, lo);
            *reinterpret_cast<uint32_t*>(g_Ah + dbase + nt * 8) = hi;
            *reinterpret_cast<uint32_t*>(g_Al + dbase + nt * 8) = lo;
        }
    }
}

// ---------------- launch ----------------
extern "C" void kernel_launch(void* const* d_in, const int* in_sizes, int n_in,
                              void* d_out, int out_size) {
    const float* x      = (const float*)d_in[0];
    const int*   segpos = (const int*)d_in[1];
    const float* qw   = (const float*)d_in[3];
    const float* kvw  = (const float*)d_in[4];
    const float* outw = (const float*)d_in[5];
    float* out = (float*)d_out;

    __nv_bfloat16 *pAh, *pAl, *pBph, *pBpl, *pBoh, *pBol, *pQh, *pQl, *pKh, *pKl;
    float* pQKV;
    cudaGetSymbolAddress((void**)&pAh, g_Ah);
    cudaGetSymbolAddress((void**)&pAl, g_Al);
    cudaGetSymbolAddress((void**)&pBph, g_Bph);
    cudaGetSymbolAddress((void**)&pBpl, g_Bpl);
    cudaGetSymbolAddress((void**)&pBoh, g_Boh);
    cudaGetSymbolAddress((void**)&pBol, g_Bol);
    cudaGetSymbolAddress((void**)&pQh, g_Qh);
    cudaGetSymbolAddress((void**)&pQl, g_Ql2);
    cudaGetSymbolAddress((void**)&pKh, g_Kh);
    cudaGetSymbolAddress((void**)&pKl, g_Kl);
    cudaGetSymbolAddress((void**)&pQKV, g_QKV);

    pack_convert<<<2048, 256>>>(x, qw, kvw, outw);

    const int GEMM_SMEM = 3 * STAGE_ELEMS * (int)sizeof(__nv_bfloat16);  // 215040
    cudaFuncSetAttribute(gemm_bf16split, cudaFuncAttributeMaxDynamicSharedMemorySize, GEMM_SMEM);

    // fused QKV projection: (2048, 4096) @ (4096, 6144)
    gemm_bf16split<<<dim3(NPROJ / 128, 16), 512, GEMM_SMEM>>>(pAh, pAl, pBph, pBpl, pQKV,
                                                              T_SEQ, NPROJ, D_MODEL);

    rope_split<<<(T_SEQ * NHEADS * 64 + 255) / 256, 256>>>(pQKV, NPROJ, 0, segpos, NHEADS,
                                                           0.08838834764831845f, pQh, pQl);
    rope_split<<<(T_SEQ * KVHEADS * 64 + 255) / 256, 256>>>(pQKV, NPROJ, 4096, segpos, KVHEADS,
                                                            1.0f, pKh, pKl);
    v_split<<<512, 256>>>();

    const int ATTN_SMEM = 2 * STAGE4 * (int)sizeof(__nv_bfloat16);  // 139264
    cudaFuncSetAttribute(attn_tc, cudaFuncAttributeMaxDynamicSharedMemorySize, ATTN_SMEM);
    attn_tc<<<dim3(NHEADS, T_SEQ / 128), 256, ATTN_SMEM>>>(segpos);

    // out projection: (2048, 4096) @ (4096, 4096)
    gemm_bf16split<<<dim3(32, 16), 512, GEMM_SMEM>>>(pAh, pAl, pBoh, pBol, out,
                                                     T_SEQ, D_MODEL, D_MODEL);
}

// round 8
// speedup vs baseline: 1.0497x; 1.0497x over previous
#include <cuda_runtime.h>
#include <cuda_bf16.h>
#include <math.h>
#include <stdint.h>

#define T_SEQ   2048
#define D_MODEL 4096
#define NHEADS  32
#define KVHEADS 8
#define HDIM    128
#define WINDOW  1024
#define NPROJ   6144   // 4096 Q + 1024 K + 1024 V

// ---------------- scratch (device globals) ----------------
__device__ __nv_bfloat16 g_Ah[T_SEQ * D_MODEL];          // A planes: X, later Enc
__device__ __nv_bfloat16 g_Al[T_SEQ * D_MODEL];
__device__ __nv_bfloat16 g_Bph[D_MODEL * NPROJ];         // packed QKV proj weights (D, 6144)
__device__ __nv_bfloat16 g_Bpl[D_MODEL * NPROJ];
__device__ __nv_bfloat16 g_Boh[D_MODEL * D_MODEL];       // out proj (N*H, D)
__device__ __nv_bfloat16 g_Bol[D_MODEL * D_MODEL];
__device__ float g_QKV[T_SEQ * NPROJ];
// attention operand planes
__device__ __nv_bfloat16 g_Qh[T_SEQ * NHEADS * HDIM];
__device__ __nv_bfloat16 g_Ql2[T_SEQ * NHEADS * HDIM];
__device__ __nv_bfloat16 g_Kh[T_SEQ * KVHEADS * HDIM];
__device__ __nv_bfloat16 g_Kl[T_SEQ * KVHEADS * HDIM];
__device__ __nv_bfloat16 g_Vh[T_SEQ * KVHEADS * HDIM];
__device__ __nv_bfloat16 g_Vl[T_SEQ * KVHEADS * HDIM];

// ---------------- helpers ----------------
__device__ __forceinline__ void split_bf16(float v, __nv_bfloat16& hi, __nv_bfloat16& lo) {
    hi = __float2bfloat16(v);
    lo = __float2bfloat16(v - __bfloat162float(hi));
}
__device__ __forceinline__ void cp16(void* dst, const void* src) {
    uint32_t d = (uint32_t)__cvta_generic_to_shared(dst);
    asm volatile("cp.async.cg.shared.global [%0], [%1], 16;\n" :: "r"(d), "l"(src));
}
__device__ __forceinline__ void cp_commit() { asm volatile("cp.async.commit_group;\n"); }

__device__ __forceinline__ void ldsm4(uint32_t& r0, uint32_t& r1, uint32_t& r2, uint32_t& r3,
                                      const __nv_bfloat16* p) {
    uint32_t a = (uint32_t)__cvta_generic_to_shared(p);
    asm volatile("ldmatrix.sync.aligned.m8n8.x4.shared.b16 {%0,%1,%2,%3}, [%4];"
                 : "=r"(r0), "=r"(r1), "=r"(r2), "=r"(r3) : "r"(a));
}
__device__ __forceinline__ void ldsm4t(uint32_t& r0, uint32_t& r1, uint32_t& r2, uint32_t& r3,
                                       const __nv_bfloat16* p) {
    uint32_t a = (uint32_t)__cvta_generic_to_shared(p);
    asm volatile("ldmatrix.sync.aligned.m8n8.x4.trans.shared.b16 {%0,%1,%2,%3}, [%4];"
                 : "=r"(r0), "=r"(r1), "=r"(r2), "=r"(r3) : "r"(a));
}
__device__ __forceinline__ void mma16816(float* c, const uint32_t* a, uint32_t b0, uint32_t b1) {
    asm volatile(
        "mma.sync.aligned.m16n8k16.row.col.f32.bf16.bf16.f32 "
        "{%0,%1,%2,%3}, {%4,%5,%6,%7}, {%8,%9}, {%0,%1,%2,%3};"
        : "+f"(c[0]), "+f"(c[1]), "+f"(c[2]), "+f"(c[3])
        : "r"(a[0]), "r"(a[1]), "r"(a[2]), "r"(a[3]), "r"(b0), "r"(b1));
}
__device__ __forceinline__ void pack_split(float a, float b, uint32_t& hi, uint32_t& lo) {
    __nv_bfloat16 ha = __float2bfloat16(a);
    __nv_bfloat16 hb = __float2bfloat16(b);
    float ra = a - __bfloat162float(ha);
    float rb = b - __bfloat162float(hb);
    __nv_bfloat162 h2 = __halves2bfloat162(ha, hb);
    __nv_bfloat162 l2 = __halves2bfloat162(__float2bfloat16(ra), __float2bfloat16(rb));
    hi = *reinterpret_cast<uint32_t*>(&h2);
    lo = *reinterpret_cast<uint32_t*>(&l2);
}

// ---------------- pack + convert all weights / X ----------------
__global__ void pack_convert(const float* __restrict__ x, const float* __restrict__ qw,
                             const float* __restrict__ kvw, const float* __restrict__ ow) {
    const int stride = gridDim.x * blockDim.x;
    const int tid = blockIdx.x * blockDim.x + threadIdx.x;

    // X -> A planes (vectorized: float2 -> bf16x2 hi/lo)
    const int NX2 = (T_SEQ * D_MODEL) >> 1;
    uint32_t* ahw = reinterpret_cast<uint32_t*>(g_Ah);
    uint32_t* alw = reinterpret_cast<uint32_t*>(g_Al);
    const float2* x2 = reinterpret_cast<const float2*>(x);
    for (int i = tid; i < NX2; i += stride) {
        float2 v = x2[i];
        pack_split(v.x, v.y, ahw[i], alw[i]);
    }

    // packed projection weights (D, 6144): d over blocks, col over threads
    for (int d = blockIdx.x; d < D_MODEL; d += gridDim.x) {
        for (int col = threadIdx.x; col < NPROJ; col += blockDim.x) {
            int h = col & 127;
            float w;
            if (col < 4096) {
                int nn = col >> 7;
                w = qw[(((size_t)nn * D_MODEL + d) << 7) + h];
            } else if (col < 5120) {
                int k = (col - 4096) >> 7;
                w = kvw[(((size_t)k * D_MODEL + d) << 7) + h];
            } else {
                int k = (col - 5120) >> 7;
                w = kvw[(((size_t)(KVHEADS + k) * D_MODEL + d) << 7) + h];
            }
            size_t i = (size_t)d * NPROJ + col;
            split_bf16(w, g_Bph[i], g_Bpl[i]);
        }
    }

    // out_w (N*H, D) row-major: vectorized straight convert
    const int NO2 = (D_MODEL * D_MODEL) >> 1;
    uint32_t* bohw = reinterpret_cast<uint32_t*>(g_Boh);
    uint32_t* bolw = reinterpret_cast<uint32_t*>(g_Bol);
    const float2* ow2 = reinterpret_cast<const float2*>(ow);
    for (int i = tid; i < NO2; i += stride) {
        float2 v = ow2[i];
        pack_split(v.x, v.y, bohw[i], bolw[i]);
    }
}

// ---------------- bf16-split tensor-core GEMM: CTA 128x256, warp 64x64 ----------------
#define SA2 72            // A smem row stride (elems)
#define SB2 264           // B smem row stride (elems): 256 + 8 pad
#define A_PLANE (128 * SA2)          // 9216
#define B_PLANE (64 * SB2)           // 16896
#define OFF2_AL A_PLANE
#define OFF2_BH (2 * A_PLANE)
#define OFF2_BL (2 * A_PLANE + B_PLANE)
#define STAGE2 (2 * A_PLANE + 2 * B_PLANE)   // 52224 elems = 104448 B

__global__ __launch_bounds__(256)
void gemm_bf16split(const __nv_bfloat16* __restrict__ Ahg, const __nv_bfloat16* __restrict__ Alg,
                    const __nv_bfloat16* __restrict__ Bhg, const __nv_bfloat16* __restrict__ Blg,
                    float* __restrict__ C, int M, int Nc, int Kd) {
    extern __shared__ __nv_bfloat16 smem[];
    const int tid  = threadIdx.x;
    const int lane = tid & 31;
    const int wid  = tid >> 5;
    const int wm   = wid >> 2;     // 0..1 -> 64-row half
    const int wn   = wid & 3;      // 0..3 -> 64-col quarter
    const int row0 = blockIdx.y * 128;
    const int n0   = blockIdx.x * 256;
    const int lrow = lane & 15;
    const int lcol = (lane >> 4) << 3;

    float acc[4][8][4];
    #pragma unroll
    for (int mt = 0; mt < 4; mt++)
        #pragma unroll
        for (int nt = 0; nt < 8; nt++)
            #pragma unroll
            for (int r = 0; r < 4; r++) acc[mt][nt][r] = 0.f;

    const int KT = Kd >> 6;

    auto stage_copy = [&](int buf, int k0) {
        __nv_bfloat16* s = smem + buf * STAGE2;
        // A: 128 rows x 64 cols, hi+lo
        #pragma unroll
        for (int c = tid; c < 1024; c += 256) {
            int r = c >> 3, col = (c & 7) << 3;
            size_t g = (size_t)(row0 + r) * Kd + k0 + col;
            cp16(s + r * SA2 + col, Ahg + g);
            cp16(s + OFF2_AL + r * SA2 + col, Alg + g);
        }
        // B: 64 k-rows x 256 cols, hi+lo
        #pragma unroll
        for (int c = tid; c < 2048; c += 256) {
            int r = c >> 5, col = (c & 31) << 3;
            size_t g = (size_t)(k0 + r) * Nc + n0 + col;
            cp16(s + OFF2_BH + r * SB2 + col, Bhg + g);
            cp16(s + OFF2_BL + r * SB2 + col, Blg + g);
        }
    };

    stage_copy(0, 0);
    cp_commit();

    for (int kt = 0; kt < KT; kt++) {
        if (kt + 1 < KT) {
            stage_copy((kt + 1) & 1, (kt + 1) << 6);
            cp_commit();
            asm volatile("cp.async.wait_group 1;\n");
        } else {
            asm volatile("cp.async.wait_group 0;\n");
        }
        __syncthreads();

        const __nv_bfloat16* s  = smem + (kt & 1) * STAGE2;
        const __nv_bfloat16* Ah = s;
        const __nv_bfloat16* Al = s + OFF2_AL;
        const __nv_bfloat16* Bh = s + OFF2_BH;
        const __nv_bfloat16* Bl = s + OFF2_BL;

        #pragma unroll
        for (int k16 = 0; k16 < 4; k16++) {
            const int kc = k16 << 4;
            uint32_t ah[4][4], al[4][4];
            #pragma unroll
            for (int mt = 0; mt < 4; mt++) {
                const __nv_bfloat16* pa = Ah + (wm * 64 + mt * 16 + lrow) * SA2 + kc + lcol;
                ldsm4(ah[mt][0], ah[mt][1], ah[mt][2], ah[mt][3], pa);
                const __nv_bfloat16* pl = Al + (wm * 64 + mt * 16 + lrow) * SA2 + kc + lcol;
                ldsm4(al[mt][0], al[mt][1], al[mt][2], al[mt][3], pl);
            }
            #pragma unroll
            for (int jt = 0; jt < 4; jt++) {
                uint32_t bh[4], bl[4];
                const __nv_bfloat16* pb = Bh + (kc + lrow) * SB2 + wn * 64 + jt * 16 + lcol;
                ldsm4t(bh[0], bh[1], bh[2], bh[3], pb);
                const __nv_bfloat16* pbl = Bl + (kc + lrow) * SB2 + wn * 64 + jt * 16 + lcol;
                ldsm4t(bl[0], bl[1], bl[2], bl[3], pbl);
                #pragma unroll
                for (int mt = 0; mt < 4; mt++) {
                    mma16816(acc[mt][2 * jt],     ah[mt], bh[0], bh[1]);
                    mma16816(acc[mt][2 * jt],     ah[mt], bl[0], bl[1]);
                    mma16816(acc[mt][2 * jt],     al[mt], bh[0], bh[1]);
                    mma16816(acc[mt][2 * jt + 1], ah[mt], bh[2], bh[3]);
                    mma16816(acc[mt][2 * jt + 1], ah[mt], bl[2], bl[3]);
                    mma16816(acc[mt][2 * jt + 1], al[mt], bh[2], bh[3]);
                }
            }
        }
        __syncthreads();
    }

    // epilogue: warp writes its 64x64 tile
    float* Cb = C + (size_t)(row0 + wm * 64) * Nc + n0 + wn * 64;
    const int g  = lane >> 2;
    const int tc = (lane & 3) * 2;
    #pragma unroll
    for (int mt = 0; mt < 4; mt++)
        #pragma unroll
        for (int nt = 0; nt < 8; nt++) {
            float2 v0 = make_float2(acc[mt][nt][0], acc[mt][nt][1]);
            float2 v1 = make_float2(acc[mt][nt][2], acc[mt][nt][3]);
            *reinterpret_cast<float2*>(Cb + (size_t)(mt * 16 + g) * Nc + nt * 8 + tc)     = v0;
            *reinterpret_cast<float2*>(Cb + (size_t)(mt * 16 + g + 8) * Nc + nt * 8 + tc) = v1;
        }
}

// ---------------- fused RoPE + scale + bf16 hi/lo split ----------------
__global__ void rope_split(const float* __restrict__ src, int srcStride, int srcOff,
                           const int* __restrict__ pos, int n_heads, float scale,
                           __nv_bfloat16* __restrict__ dh, __nv_bfloat16* __restrict__ dl) {
    int idx = blockIdx.x * blockDim.x + threadIdx.x;
    int total = T_SEQ * n_heads * 64;
    if (idx >= total) return;
    int hh = idx & 63;
    int nh = (idx >> 6) % n_heads;
    int t  = idx / (n_heads << 6);
    float ts  = powf(10000.0f, (float)hh * (1.0f / 64.0f));
    float ang = (float)pos[t] / ts;
    float sv = sinf(ang), cv = cosf(ang);
    size_t sbase = (size_t)t * srcStride + srcOff + nh * HDIM;
    size_t dbase = (size_t)t * (n_heads * HDIM) + nh * HDIM;
    float a = src[sbase + hh], b = src[sbase + hh + 64];
    float o1 = (a * cv - b * sv) * scale;
    float o2 = (b * cv + a * sv) * scale;
    split_bf16(o1, dh[dbase + hh], dl[dbase + hh]);
    split_bf16(o2, dh[dbase + hh + 64], dl[dbase + hh + 64]);
}

__global__ void v_split() {
    int stride = gridDim.x * blockDim.x;
    int tid = blockIdx.x * blockDim.x + threadIdx.x;
    const int N = T_SEQ * KVHEADS * HDIM;
    for (int i = tid; i < N; i += stride) {
        int t = i >> 10, c = i & 1023;
        split_bf16(g_QKV[(size_t)t * NPROJ + 5120 + c], g_Vh[i], g_Vl[i]);
    }
}

// ---------------- tensor-core flash attention (unchanged) ----------------
#define AST 136
#define PLANE (64 * AST)
#define STAGE4 (4 * PLANE)

__global__ __launch_bounds__(256, 1)
void attn_tc(const int* __restrict__ segpos) {
    extern __shared__ __nv_bfloat16 dsm[];
    __shared__ int sp[128];
    __shared__ int s_pmin, s_pmax;

    const int n   = blockIdx.x;
    const int t0  = blockIdx.y * 128;
    const int kvh = n >> 2;
    const int tid = threadIdx.x;
    const int lane = tid & 31;
    const int w = tid >> 5;
    const int g8 = lane >> 2;
    const int q2 = (lane & 3) << 1;

    if (tid < 128) sp[tid] = segpos[t0 + tid];
    __syncthreads();
    if (tid == 0) {
        int mn = sp[0], mx = sp[0];
        for (int i = 1; i < 128; i++) { int v = sp[i]; mn = min(mn, v); mx = max(mx, v); }
        s_pmin = mn; s_pmax = mx;
    }
    __syncthreads();

    const int row0 = t0 + w * 16 + g8;
    uint32_t qh[8][4], ql[8][4];
    {
        const __nv_bfloat16* qb  = g_Qh  + (size_t)row0 * D_MODEL + n * HDIM;
        const __nv_bfloat16* qb8 = qb + (size_t)8 * D_MODEL;
        const __nv_bfloat16* lb  = g_Ql2 + (size_t)row0 * D_MODEL + n * HDIM;
        const __nv_bfloat16* lb8 = lb + (size_t)8 * D_MODEL;
        #pragma unroll
        for (int k16 = 0; k16 < 8; k16++) {
            int c0 = k16 * 16 + q2;
            qh[k16][0] = *reinterpret_cast<const uint32_t*>(qb  + c0);
            qh[k16][1] = *reinterpret_cast<const uint32_t*>(qb8 + c0);
            qh[k16][2] = *reinterpret_cast<const uint32_t*>(qb  + c0 + 8);
            qh[k16][3] = *reinterpret_cast<const uint32_t*>(qb8 + c0 + 8);
            ql[k16][0] = *reinterpret_cast<const uint32_t*>(lb  + c0);
            ql[k16][1] = *reinterpret_cast<const uint32_t*>(lb8 + c0);
            ql[k16][2] = *reinterpret_cast<const uint32_t*>(lb  + c0 + 8);
            ql[k16][3] = *reinterpret_cast<const uint32_t*>(lb8 + c0 + 8);
        }
    }

    float m[2]    = {-1e30f, -1e30f};
    float lsum[2] = {0.f, 0.f};
    float O[16][4];
    #pragma unroll
    for (int i = 0; i < 16; i++)
        #pragma unroll
        for (int j = 0; j < 4; j++) O[i][j] = 0.f;

    int s_lo = s_pmin - (WINDOW - 1); if (s_lo < 0) s_lo = 0;
    const int sb = s_lo & ~63;
    const int nIter = ((t0 + 127 - sb) >> 6) + 1;

    auto loadKV = [&](int stage, int s0) {
        __nv_bfloat16* base = dsm + stage * STAGE4;
        #pragma unroll
        for (int i = tid; i < 1024; i += 256) {
            int r = i >> 4, c = (i & 15) << 3;
            size_t g = (size_t)(s0 + r) * (KVHEADS * HDIM) + kvh * HDIM + c;
            cp16(base + r * AST + c,             g_Kh + g);
            cp16(base + PLANE + r * AST + c,     g_Kl + g);
            cp16(base + 2 * PLANE + r * AST + c, g_Vh + g);
            cp16(base + 3 * PLANE + r * AST + c, g_Vl + g);
        }
    };

    loadKV(0, sb); cp_commit();
    if (nIter > 1) { loadKV(1, sb + 64); cp_commit(); }

    const int krow = (lane & 7) + ((lane & 16) ? 8 : 0);
    const int ksel = (lane & 8) ? 8 : 0;
    const int vkey = lane & 15;
    const int vsel = (lane & 16) ? 8 : 0;

    for (int it = 0; it < nIter; it++) {
        const int s0 = sb + (it << 6);
        if (it + 1 < nIter) asm volatile("cp.async.wait_group 1;\n");
        else                asm volatile("cp.async.wait_group 0;\n");
        __syncthreads();

        const __nv_bfloat16* base = dsm + (it & 1) * STAGE4;
        const __nv_bfloat16* Kh = base;
        const __nv_bfloat16* Kl = base + PLANE;
        const __nv_bfloat16* Vh = base + 2 * PLANE;
        const __nv_bfloat16* Vl = base + 3 * PLANE;

        float S[8][4];
        #pragma unroll
        for (int i = 0; i < 8; i++)
            #pragma unroll
            for (int j = 0; j < 4; j++) S[i][j] = 0.f;

        #pragma unroll
        for (int k16 = 0; k16 < 8; k16++) {
            #pragma unroll
            for (int nt = 0; nt < 4; nt++) {
                uint32_t bh[4], bl[4];
                int koff = (nt * 16 + krow) * AST + k16 * 16 + ksel;
                ldsm4(bh[0], bh[1], bh[2], bh[3], Kh + koff);
                ldsm4(bl[0], bl[1], bl[2], bl[3], Kl + koff);
                mma16816(S[2 * nt],     qh[k16], bh[0], bh[1]);
                mma16816(S[2 * nt],     qh[k16], bl[0], bl[1]);
                mma16816(S[2 * nt],     ql[k16], bh[0], bh[1]);
                mma16816(S[2 * nt + 1], qh[k16], bh[2], bh[3]);
                mma16816(S[2 * nt + 1], qh[k16], bl[2], bl[3]);
                mma16816(S[2 * nt + 1], ql[k16], bh[2], bh[3]);
            }
        }

        const bool interior = (s0 + 63 <= t0) && (s0 > s_pmax - WINDOW) && (s0 + 63 < s_pmin + WINDOW);
        if (interior) {
            #pragma unroll
            for (int nt = 0; nt < 8; nt++)
                #pragma unroll
                for (int jj = 0; jj < 4; jj++) {
                    float e = __expf(S[nt][jj] * 0.04f);
                    S[nt][jj] = 50.f - __fdividef(100.f, e + 1.f);
                }
        } else {
            const int sp_r0 = sp[w * 16 + g8];
            const int sp_r1 = sp[w * 16 + g8 + 8];
            #pragma unroll
            for (int nt = 0; nt < 8; nt++) {
                int scol0 = s0 + nt * 8 + q2;
                #pragma unroll
                for (int jj = 0; jj < 4; jj++) {
                    int s = scol0 + (jj & 1);
                    int t = row0 + ((jj & 2) ? 8 : 0);
                    int p = (jj & 2) ? sp_r1 : sp_r0;
                    float e = __expf(S[nt][jj] * 0.04f);
                    float c = 50.f - __fdividef(100.f, e + 1.f);
                    bool ok = (s <= t) && (s > p - WINDOW) && (s < p + WINDOW);
                    S[nt][jj] = ok ? c : -1e30f;
                }
            }
        }

        #pragma unroll
        for (int h = 0; h < 2; h++) {
            float mx = -1e30f;
            #pragma unroll
            for (int nt = 0; nt < 8; nt++)
                mx = fmaxf(mx, fmaxf(S[nt][2 * h], S[nt][2 * h + 1]));
            mx = fmaxf(mx, __shfl_xor_sync(0xffffffffu, mx, 1));
            mx = fmaxf(mx, __shfl_xor_sync(0xffffffffu, mx, 2));
            float mnew  = fmaxf(m[h], mx);
            float alpha = __expf(m[h] - mnew);
            float rs = 0.f;
            #pragma unroll
            for (int nt = 0; nt < 8; nt++) {
                #pragma unroll
                for (int e2 = 0; e2 < 2; e2++) {
                    float sv = S[nt][2 * h + e2];
                    float pv = (sv < -9e29f) ? 0.f : __expf(sv - mnew);
                    S[nt][2 * h + e2] = pv;
                    rs += pv;
                }
            }
            rs += __shfl_xor_sync(0xffffffffu, rs, 1);
            rs += __shfl_xor_sync(0xffffffffu, rs, 2);
            lsum[h] = lsum[h] * alpha + rs;
            #pragma unroll
            for (int nt = 0; nt < 16; nt++) {
                O[nt][2 * h]     *= alpha;
                O[nt][2 * h + 1] *= alpha;
            }
            m[h] = mnew;
        }

        #pragma unroll
        for (int kt = 0; kt < 4; kt++) {
            uint32_t pah[4], pal[4];
            pack_split(S[2 * kt][0],     S[2 * kt][1],     pah[0], pal[0]);
            pack_split(S[2 * kt][2],     S[2 * kt][3],     pah[1], pal[1]);
            pack_split(S[2 * kt + 1][0], S[2 * kt + 1][1], pah[2], pal[2]);
            pack_split(S[2 * kt + 1][2], S[2 * kt + 1][3], pah[3], pal[3]);
            #pragma unroll
            for (int ht = 0; ht < 8; ht++) {
                uint32_t vh[4], vl[4];
                int voff = (kt * 16 + vkey) * AST + ht * 16 + vsel;
                ldsm4t(vh[0], vh[1], vh[2], vh[3], Vh + voff);
                ldsm4t(vl[0], vl[1], vl[2], vl[3], Vl + voff);
                mma16816(O[2 * ht],     pah, vh[0], vh[1]);
                mma16816(O[2 * ht],     pah, vl[0], vl[1]);
                mma16816(O[2 * ht],     pal, vh[0], vh[1]);
                mma16816(O[2 * ht + 1], pah, vh[2], vh[3]);
                mma16816(O[2 * ht + 1], pah, vl[2], vl[3]);
                mma16816(O[2 * ht + 1], pal, vh[2], vh[3]);
            }
        }
        __syncthreads();
        if (it + 2 < nIter) { loadKV(it & 1, s0 + 128); cp_commit(); }
    }

    #pragma unroll
    for (int h = 0; h < 2; h++) {
        float inv = 1.0f / lsum[h];
        int row = row0 + 8 * h;
        size_t dbase = (size_t)row * D_MODEL + n * HDIM + q2;
        #pragma unroll
        for (int nt = 0; nt < 16; nt++) {
            uint32_t hi, lo;
            pack_split(O[nt][2 * h] * inv, O[nt][2 * h + 1] * inv, hi, lo);
            *reinterpret_cast<uint32_t*>(g_Ah + dbase + nt * 8) = hi;
            *reinterpret_cast<uint32_t*>(g_Al + dbase + nt * 8) = lo;
        }
    }
}

// ---------------- launch ----------------
extern "C" void kernel_launch(void* const* d_in, const int* in_sizes, int n_in,
                              void* d_out, int out_size) {
    const float* x      = (const float*)d_in[0];
    const int*   segpos = (const int*)d_in[1];
    const float* qw   = (const float*)d_in[3];
    const float* kvw  = (const float*)d_in[4];
    const float* outw = (const float*)d_in[5];
    float* out = (float*)d_out;

    __nv_bfloat16 *pAh, *pAl, *pBph, *pBpl, *pBoh, *pBol, *pQh, *pQl, *pKh, *pKl;
    float* pQKV;
    cudaGetSymbolAddress((void**)&pAh, g_Ah);
    cudaGetSymbolAddress((void**)&pAl, g_Al);
    cudaGetSymbolAddress((void**)&pBph, g_Bph);
    cudaGetSymbolAddress((void**)&pBpl, g_Bpl);
    cudaGetSymbolAddress((void**)&pBoh, g_Boh);
    cudaGetSymbolAddress((void**)&pBol, g_Bol);
    cudaGetSymbolAddress((void**)&pQh, g_Qh);
    cudaGetSymbolAddress((void**)&pQl, g_Ql2);
    cudaGetSymbolAddress((void**)&pKh, g_Kh);
    cudaGetSymbolAddress((void**)&pKl, g_Kl);
    cudaGetSymbolAddress((void**)&pQKV, g_QKV);

    pack_convert<<<2048, 256>>>(x, qw, kvw, outw);

    const int GEMM_SMEM = 2 * STAGE2 * (int)sizeof(__nv_bfloat16);  // 208896
    cudaFuncSetAttribute(gemm_bf16split, cudaFuncAttributeMaxDynamicSharedMemorySize, GEMM_SMEM);

    // fused QKV projection: (2048, 4096) @ (4096, 6144), 256-wide column tiles
    gemm_bf16split<<<dim3(NPROJ / 256, T_SEQ / 128), 256, GEMM_SMEM>>>(pAh, pAl, pBph, pBpl, pQKV,
                                                                       T_SEQ, NPROJ, D_MODEL);

    rope_split<<<(T_SEQ * NHEADS * 64 + 255) / 256, 256>>>(pQKV, NPROJ, 0, segpos, NHEADS,
                                                           0.08838834764831845f, pQh, pQl);
    rope_split<<<(T_SEQ * KVHEADS * 64 + 255) / 256, 256>>>(pQKV, NPROJ, 4096, segpos, KVHEADS,
                                                            1.0f, pKh, pKl);
    v_split<<<512, 256>>>();

    const int ATTN_SMEM = 2 * STAGE4 * (int)sizeof(__nv_bfloat16);  // 139264
    cudaFuncSetAttribute(attn_tc, cudaFuncAttributeMaxDynamicSharedMemorySize, ATTN_SMEM);
    attn_tc<<<dim3(NHEADS, T_SEQ / 128), 256, ATTN_SMEM>>>(segpos);

    // out projection: (2048, 4096) @ (4096, 4096)
    gemm_bf16split<<<dim3(D_MODEL / 256, T_SEQ / 128), 256, GEMM_SMEM>>>(pAh, pAl, pBoh, pBol, out,
                                                                         T_SEQ, D_MODEL, D_MODEL);
}

// round 9
// speedup vs baseline: 1.4739x; 1.4040x over previous
#include <cuda_runtime.h>
#include <cuda_fp16.h>
#include <math.h>
#include <stdint.h>

#define T_SEQ   2048
#define D_MODEL 4096
#define NHEADS  32
#define KVHEADS 8
#define HDIM    128
#define WINDOW  1024
#define NPROJ   6144   // 4096 Q + 1024 K + 1024 V

// ---------------- scratch (device globals) ----------------
__device__ __half g_Ah[T_SEQ * D_MODEL];          // A planes (hi/lo): X, later Enc
__device__ __half g_Al[T_SEQ * D_MODEL];
__device__ __half g_Bp[D_MODEL * NPROJ];          // packed QKV proj weights (D, 6144), single plane
__device__ __half g_Bo[D_MODEL * D_MODEL];        // out proj (N*H, D), single plane
__device__ float  g_QKV[T_SEQ * NPROJ];
// attention operands
__device__ __half g_Qh[T_SEQ * NHEADS * HDIM];    // Q hi
__device__ __half g_Ql2[T_SEQ * NHEADS * HDIM];   // Q lo
__device__ __half g_Ks[T_SEQ * KVHEADS * HDIM];   // K single
__device__ __half g_Vs[T_SEQ * KVHEADS * HDIM];   // V single

// ---------------- helpers ----------------
__device__ __forceinline__ void split_fp16(float v, __half& hi, __half& lo) {
    hi = __float2half_rn(v);
    lo = __float2half_rn(v - __half2float(hi));
}
__device__ __forceinline__ void cp16(void* dst, const void* src) {
    uint32_t d = (uint32_t)__cvta_generic_to_shared(dst);
    asm volatile("cp.async.cg.shared.global [%0], [%1], 16;\n" :: "r"(d), "l"(src));
}
__device__ __forceinline__ void cp_commit() { asm volatile("cp.async.commit_group;\n"); }

__device__ __forceinline__ void ldsm4(uint32_t& r0, uint32_t& r1, uint32_t& r2, uint32_t& r3,
                                      const __half* p) {
    uint32_t a = (uint32_t)__cvta_generic_to_shared(p);
    asm volatile("ldmatrix.sync.aligned.m8n8.x4.shared.b16 {%0,%1,%2,%3}, [%4];"
                 : "=r"(r0), "=r"(r1), "=r"(r2), "=r"(r3) : "r"(a));
}
__device__ __forceinline__ void ldsm4t(uint32_t& r0, uint32_t& r1, uint32_t& r2, uint32_t& r3,
                                       const __half* p) {
    uint32_t a = (uint32_t)__cvta_generic_to_shared(p);
    asm volatile("ldmatrix.sync.aligned.m8n8.x4.trans.shared.b16 {%0,%1,%2,%3}, [%4];"
                 : "=r"(r0), "=r"(r1), "=r"(r2), "=r"(r3) : "r"(a));
}
__device__ __forceinline__ void mma16816(float* c, const uint32_t* a, uint32_t b0, uint32_t b1) {
    asm volatile(
        "mma.sync.aligned.m16n8k16.row.col.f32.f16.f16.f32 "
        "{%0,%1,%2,%3}, {%4,%5,%6,%7}, {%8,%9}, {%0,%1,%2,%3};"
        : "+f"(c[0]), "+f"(c[1]), "+f"(c[2]), "+f"(c[3])
        : "r"(a[0]), "r"(a[1]), "r"(a[2]), "r"(a[3]), "r"(b0), "r"(b1));
}
__device__ __forceinline__ void pack_split(float a, float b, uint32_t& hi, uint32_t& lo) {
    __half ha = __float2half_rn(a);
    __half hb = __float2half_rn(b);
    float ra = a - __half2float(ha);
    float rb = b - __half2float(hb);
    __half2 h2 = __halves2half2(ha, hb);
    __half2 l2 = __halves2half2(__float2half_rn(ra), __float2half_rn(rb));
    hi = *reinterpret_cast<uint32_t*>(&h2);
    lo = *reinterpret_cast<uint32_t*>(&l2);
}

// ---------------- pack + convert all weights / X ----------------
__global__ void pack_convert(const float* __restrict__ x, const float* __restrict__ qw,
                             const float* __restrict__ kvw, const float* __restrict__ ow) {
    const int stride = gridDim.x * blockDim.x;
    const int tid = blockIdx.x * blockDim.x + threadIdx.x;

    // X -> A hi/lo planes (vectorized)
    const int NX2 = (T_SEQ * D_MODEL) >> 1;
    uint32_t* ahw = reinterpret_cast<uint32_t*>(g_Ah);
    uint32_t* alw = reinterpret_cast<uint32_t*>(g_Al);
    const float2* x2 = reinterpret_cast<const float2*>(x);
    for (int i = tid; i < NX2; i += stride) {
        float2 v = x2[i];
        pack_split(v.x, v.y, ahw[i], alw[i]);
    }

    // packed projection weights (D, 6144): single fp16 plane
    for (int d = blockIdx.x; d < D_MODEL; d += gridDim.x) {
        for (int col = threadIdx.x; col < NPROJ; col += blockDim.x) {
            int h = col & 127;
            float w;
            if (col < 4096) {
                int nn = col >> 7;
                w = qw[(((size_t)nn * D_MODEL + d) << 7) + h];
            } else if (col < 5120) {
                int k = (col - 4096) >> 7;
                w = kvw[(((size_t)k * D_MODEL + d) << 7) + h];
            } else {
                int k = (col - 5120) >> 7;
                w = kvw[(((size_t)(KVHEADS + k) * D_MODEL + d) << 7) + h];
            }
            g_Bp[(size_t)d * NPROJ + col] = __float2half_rn(w);
        }
    }

    // out_w (N*H, D): single fp16 plane, vectorized
    const int NO2 = (D_MODEL * D_MODEL) >> 1;
    uint32_t* bow = reinterpret_cast<uint32_t*>(g_Bo);
    const float2* ow2 = reinterpret_cast<const float2*>(ow);
    for (int i = tid; i < NO2; i += stride) {
        float2 v = ow2[i];
        __half2 h2 = __halves2half2(__float2half_rn(v.x), __float2half_rn(v.y));
        bow[i] = *reinterpret_cast<uint32_t*>(&h2);
    }
}

// ---------------- fp16 asymmetric-split GEMM: CTA 128x256, warp 64x64 ----------------
// C = (Ah+Al) @ B ; A hi/lo fp16 (near-exact), B single fp16. 2 MMAs per tile-product.
#define SA2 72
#define SB2 264
#define A_PLANE (128 * SA2)                  // 9216
#define B_PLANE (64 * SB2)                   // 16896
#define OFF2_AL A_PLANE
#define OFF2_B  (2 * A_PLANE)
#define STAGE2 (2 * A_PLANE + B_PLANE)       // 35328 elems = 70656 B

__global__ __launch_bounds__(256)
void gemm_fp16split(const __half* __restrict__ Ahg, const __half* __restrict__ Alg,
                    const __half* __restrict__ Bg,
                    float* __restrict__ C, int M, int Nc, int Kd) {
    extern __shared__ __half smem[];
    const int tid  = threadIdx.x;
    const int lane = tid & 31;
    const int wid  = tid >> 5;
    const int wm   = wid >> 2;     // 0..1
    const int wn   = wid & 3;      // 0..3
    const int row0 = blockIdx.y * 128;
    const int n0   = blockIdx.x * 256;
    const int lrow = lane & 15;
    const int lcol = (lane >> 4) << 3;

    float acc[4][8][4];
    #pragma unroll
    for (int mt = 0; mt < 4; mt++)
        #pragma unroll
        for (int nt = 0; nt < 8; nt++)
            #pragma unroll
            for (int r = 0; r < 4; r++) acc[mt][nt][r] = 0.f;

    const int KT = Kd >> 6;

    auto stage_copy = [&](int buf, int k0) {
        __half* s = smem + buf * STAGE2;
        #pragma unroll
        for (int c = tid; c < 1024; c += 256) {
            int r = c >> 3, col = (c & 7) << 3;
            size_t g = (size_t)(row0 + r) * Kd + k0 + col;
            cp16(s + r * SA2 + col, Ahg + g);
            cp16(s + OFF2_AL + r * SA2 + col, Alg + g);
        }
        #pragma unroll
        for (int c = tid; c < 2048; c += 256) {
            int r = c >> 5, col = (c & 31) << 3;
            size_t g = (size_t)(k0 + r) * Nc + n0 + col;
            cp16(s + OFF2_B + r * SB2 + col, Bg + g);
        }
    };

    stage_copy(0, 0);
    cp_commit();

    for (int kt = 0; kt < KT; kt++) {
        if (kt + 1 < KT) {
            stage_copy((kt + 1) & 1, (kt + 1) << 6);
            cp_commit();
            asm volatile("cp.async.wait_group 1;\n");
        } else {
            asm volatile("cp.async.wait_group 0;\n");
        }
        __syncthreads();

        const __half* s  = smem + (kt & 1) * STAGE2;
        const __half* Ah = s;
        const __half* Al = s + OFF2_AL;
        const __half* Bs = s + OFF2_B;

        #pragma unroll
        for (int k16 = 0; k16 < 4; k16++) {
            const int kc = k16 << 4;
            uint32_t ah[4][4], al[4][4];
            #pragma unroll
            for (int mt = 0; mt < 4; mt++) {
                const __half* pa = Ah + (wm * 64 + mt * 16 + lrow) * SA2 + kc + lcol;
                ldsm4(ah[mt][0], ah[mt][1], ah[mt][2], ah[mt][3], pa);
                const __half* pl = Al + (wm * 64 + mt * 16 + lrow) * SA2 + kc + lcol;
                ldsm4(al[mt][0], al[mt][1], al[mt][2], al[mt][3], pl);
            }
            #pragma unroll
            for (int jt = 0; jt < 4; jt++) {
                uint32_t bh[4];
                const __half* pb = Bs + (kc + lrow) * SB2 + wn * 64 + jt * 16 + lcol;
                ldsm4t(bh[0], bh[1], bh[2], bh[3], pb);
                #pragma unroll
                for (int mt = 0; mt < 4; mt++) {
                    mma16816(acc[mt][2 * jt],     ah[mt], bh[0], bh[1]);
                    mma16816(acc[mt][2 * jt],     al[mt], bh[0], bh[1]);
                    mma16816(acc[mt][2 * jt + 1], ah[mt], bh[2], bh[3]);
                    mma16816(acc[mt][2 * jt + 1], al[mt], bh[2], bh[3]);
                }
            }
        }
        __syncthreads();
    }

    float* Cb = C + (size_t)(row0 + wm * 64) * Nc + n0 + wn * 64;
    const int g  = lane >> 2;
    const int tc = (lane & 3) * 2;
    #pragma unroll
    for (int mt = 0; mt < 4; mt++)
        #pragma unroll
        for (int nt = 0; nt < 8; nt++) {
            float2 v0 = make_float2(acc[mt][nt][0], acc[mt][nt][1]);
            float2 v1 = make_float2(acc[mt][nt][2], acc[mt][nt][3]);
            *reinterpret_cast<float2*>(Cb + (size_t)(mt * 16 + g) * Nc + nt * 8 + tc)     = v0;
            *reinterpret_cast<float2*>(Cb + (size_t)(mt * 16 + g + 8) * Nc + nt * 8 + tc) = v1;
        }
}

// ---------------- fused RoPE + scale + fp16 output (split if dl != null) ----------------
__global__ void rope_split(const float* __restrict__ src, int srcStride, int srcOff,
                           const int* __restrict__ pos, int n_heads, float scale,
                           __half* __restrict__ dh, __half* __restrict__ dl) {
    int idx = blockIdx.x * blockDim.x + threadIdx.x;
    int total = T_SEQ * n_heads * 64;
    if (idx >= total) return;
    int hh = idx & 63;
    int nh = (idx >> 6) % n_heads;
    int t  = idx / (n_heads << 6);
    float ts  = powf(10000.0f, (float)hh * (1.0f / 64.0f));
    float ang = (float)pos[t] / ts;
    float sv = sinf(ang), cv = cosf(ang);
    size_t sbase = (size_t)t * srcStride + srcOff + nh * HDIM;
    size_t dbase = (size_t)t * (n_heads * HDIM) + nh * HDIM;
    float a = src[sbase + hh], b = src[sbase + hh + 64];
    float o1 = (a * cv - b * sv) * scale;
    float o2 = (b * cv + a * sv) * scale;
    if (dl) {
        split_fp16(o1, dh[dbase + hh], dl[dbase + hh]);
        split_fp16(o2, dh[dbase + hh + 64], dl[dbase + hh + 64]);
    } else {
        dh[dbase + hh]      = __float2half_rn(o1);
        dh[dbase + hh + 64] = __float2half_rn(o2);
    }
}

__global__ void v_split() {
    int stride = gridDim.x * blockDim.x;
    int tid = blockIdx.x * blockDim.x + threadIdx.x;
    const int N = T_SEQ * KVHEADS * HDIM;
    for (int i = tid; i < N; i += stride) {
        int t = i >> 10, c = i & 1023;
        g_Vs[i] = __float2half_rn(g_QKV[(size_t)t * NPROJ + 5120 + c]);
    }
}

// ---------------- fp16 tensor-core flash attention ----------------
#define AST 136
#define PLANE (64 * AST)
#define STAGE2A (2 * PLANE)   // K + V single planes

__global__ __launch_bounds__(256, 1)
void attn_tc(const int* __restrict__ segpos) {
    extern __shared__ __half dsm[];
    __shared__ int sp[128];
    __shared__ int s_pmin, s_pmax;

    const int n   = blockIdx.x;
    const int t0  = blockIdx.y * 128;
    const int kvh = n >> 2;
    const int tid = threadIdx.x;
    const int lane = tid & 31;
    const int w = tid >> 5;
    const int g8 = lane >> 2;
    const int q2 = (lane & 3) << 1;

    if (tid < 128) sp[tid] = segpos[t0 + tid];
    __syncthreads();
    if (tid == 0) {
        int mn = sp[0], mx = sp[0];
        for (int i = 1; i < 128; i++) { int v = sp[i]; mn = min(mn, v); mx = max(mx, v); }
        s_pmin = mn; s_pmax = mx;
    }
    __syncthreads();

    // Q fragments (hi/lo) -> registers, loaded once from gmem
    const int row0 = t0 + w * 16 + g8;
    uint32_t qh[8][4], ql[8][4];
    {
        const __half* qb  = g_Qh  + (size_t)row0 * D_MODEL + n * HDIM;
        const __half* qb8 = qb + (size_t)8 * D_MODEL;
        const __half* lb  = g_Ql2 + (size_t)row0 * D_MODEL + n * HDIM;
        const __half* lb8 = lb + (size_t)8 * D_MODEL;
        #pragma unroll
        for (int k16 = 0; k16 < 8; k16++) {
            int c0 = k16 * 16 + q2;
            qh[k16][0] = *reinterpret_cast<const uint32_t*>(qb  + c0);
            qh[k16][1] = *reinterpret_cast<const uint32_t*>(qb8 + c0);
            qh[k16][2] = *reinterpret_cast<const uint32_t*>(qb  + c0 + 8);
            qh[k16][3] = *reinterpret_cast<const uint32_t*>(qb8 + c0 + 8);
            ql[k16][0] = *reinterpret_cast<const uint32_t*>(lb  + c0);
            ql[k16][1] = *reinterpret_cast<const uint32_t*>(lb8 + c0);
            ql[k16][2] = *reinterpret_cast<const uint32_t*>(lb  + c0 + 8);
            ql[k16][3] = *reinterpret_cast<const uint32_t*>(lb8 + c0 + 8);
        }
    }

    float m[2]    = {-1e30f, -1e30f};
    float lsum[2] = {0.f, 0.f};
    float O[16][4];
    #pragma unroll
    for (int i = 0; i < 16; i++)
        #pragma unroll
        for (int j = 0; j < 4; j++) O[i][j] = 0.f;

    int s_lo = s_pmin - (WINDOW - 1); if (s_lo < 0) s_lo = 0;
    const int sb = s_lo & ~63;
    const int nIter = ((t0 + 127 - sb) >> 6) + 1;

    auto loadKV = [&](int stage, int s0) {
        __half* base = dsm + stage * STAGE2A;
        #pragma unroll
        for (int i = tid; i < 1024; i += 256) {
            int r = i >> 4, c = (i & 15) << 3;
            size_t g = (size_t)(s0 + r) * (KVHEADS * HDIM) + kvh * HDIM + c;
            cp16(base + r * AST + c,         g_Ks + g);
            cp16(base + PLANE + r * AST + c, g_Vs + g);
        }
    };

    loadKV(0, sb); cp_commit();
    if (nIter > 1) { loadKV(1, sb + 64); cp_commit(); }

    const int krow = (lane & 7) + ((lane & 16) ? 8 : 0);
    const int ksel = (lane & 8) ? 8 : 0;
    const int vkey = lane & 15;
    const int vsel = (lane & 16) ? 8 : 0;

    for (int it = 0; it < nIter; it++) {
        const int s0 = sb + (it << 6);
        if (it + 1 < nIter) asm volatile("cp.async.wait_group 1;\n");
        else                asm volatile("cp.async.wait_group 0;\n");
        __syncthreads();

        const __half* base = dsm + (it & 1) * STAGE2A;
        const __half* Ks = base;
        const __half* Vsm = base + PLANE;

        // ---- S = Q K^T (2 MMA: qh + ql against single K) ----
        float S[8][4];
        #pragma unroll
        for (int i = 0; i < 8; i++)
            #pragma unroll
            for (int j = 0; j < 4; j++) S[i][j] = 0.f;

        #pragma unroll
        for (int k16 = 0; k16 < 8; k16++) {
            #pragma unroll
            for (int nt = 0; nt < 4; nt++) {
                uint32_t bh[4];
                int koff = (nt * 16 + krow) * AST + k16 * 16 + ksel;
                ldsm4(bh[0], bh[1], bh[2], bh[3], Ks + koff);
                mma16816(S[2 * nt],     qh[k16], bh[0], bh[1]);
                mma16816(S[2 * nt],     ql[k16], bh[0], bh[1]);
                mma16816(S[2 * nt + 1], qh[k16], bh[2], bh[3]);
                mma16816(S[2 * nt + 1], ql[k16], bh[2], bh[3]);
            }
        }

        // ---- softcap (+mask on border blocks) ----
        const bool interior = (s0 + 63 <= t0) && (s0 > s_pmax - WINDOW) && (s0 + 63 < s_pmin + WINDOW);
        if (interior) {
            #pragma unroll
            for (int nt = 0; nt < 8; nt++)
                #pragma unroll
                for (int jj = 0; jj < 4; jj++) {
                    float e = __expf(S[nt][jj] * 0.04f);
                    S[nt][jj] = 50.f - __fdividef(100.f, e + 1.f);
                }
        } else {
            const int sp_r0 = sp[w * 16 + g8];
            const int sp_r1 = sp[w * 16 + g8 + 8];
            #pragma unroll
            for (int nt = 0; nt < 8; nt++) {
                int scol0 = s0 + nt * 8 + q2;
                #pragma unroll
                for (int jj = 0; jj < 4; jj++) {
                    int s = scol0 + (jj & 1);
                    int t = row0 + ((jj & 2) ? 8 : 0);
                    int p = (jj & 2) ? sp_r1 : sp_r0;
                    float e = __expf(S[nt][jj] * 0.04f);
                    float c = 50.f - __fdividef(100.f, e + 1.f);
                    bool ok = (s <= t) && (s > p - WINDOW) && (s < p + WINDOW);
                    S[nt][jj] = ok ? c : -1e30f;
                }
            }
        }

        // ---- online softmax ----
        #pragma unroll
        for (int h = 0; h < 2; h++) {
            float mx = -1e30f;
            #pragma unroll
            for (int nt = 0; nt < 8; nt++)
                mx = fmaxf(mx, fmaxf(S[nt][2 * h], S[nt][2 * h + 1]));
            mx = fmaxf(mx, __shfl_xor_sync(0xffffffffu, mx, 1));
            mx = fmaxf(mx, __shfl_xor_sync(0xffffffffu, mx, 2));
            float mnew  = fmaxf(m[h], mx);
            float alpha = __expf(m[h] - mnew);
            float rs = 0.f;
            #pragma unroll
            for (int nt = 0; nt < 8; nt++) {
                #pragma unroll
                for (int e2 = 0; e2 < 2; e2++) {
                    float sv = S[nt][2 * h + e2];
                    float pv = (sv < -9e29f) ? 0.f : __expf(sv - mnew);
                    S[nt][2 * h + e2] = pv;
                    rs += pv;
                }
            }
            rs += __shfl_xor_sync(0xffffffffu, rs, 1);
            rs += __shfl_xor_sync(0xffffffffu, rs, 2);
            lsum[h] = lsum[h] * alpha + rs;
            #pragma unroll
            for (int nt = 0; nt < 16; nt++) {
                O[nt][2 * h]     *= alpha;
                O[nt][2 * h + 1] *= alpha;
            }
            m[h] = mnew;
        }

        // ---- O += P V (P split hi/lo, V single: 2 MMA) ----
        #pragma unroll
        for (int kt = 0; kt < 4; kt++) {
            uint32_t pah[4], pal[4];
            pack_split(S[2 * kt][0],     S[2 * kt][1],     pah[0], pal[0]);
            pack_split(S[2 * kt][2],     S[2 * kt][3],     pah[1], pal[1]);
            pack_split(S[2 * kt + 1][0], S[2 * kt + 1][1], pah[2], pal[2]);
            pack_split(S[2 * kt + 1][2], S[2 * kt + 1][3], pah[3], pal[3]);
            #pragma unroll
            for (int ht = 0; ht < 8; ht++) {
                uint32_t vh[4];
                int voff = (kt * 16 + vkey) * AST + ht * 16 + vsel;
                ldsm4t(vh[0], vh[1], vh[2], vh[3], Vsm + voff);
                mma16816(O[2 * ht],     pah, vh[0], vh[1]);
                mma16816(O[2 * ht],     pal, vh[0], vh[1]);
                mma16816(O[2 * ht + 1], pah, vh[2], vh[3]);
                mma16816(O[2 * ht + 1], pal, vh[2], vh[3]);
            }
        }
        __syncthreads();
        if (it + 2 < nIter) { loadKV(it & 1, s0 + 128); cp_commit(); }
    }

    // ---- epilogue: write Enc hi/lo planes directly ----
    #pragma unroll
    for (int h = 0; h < 2; h++) {
        float inv = 1.0f / lsum[h];
        int row = row0 + 8 * h;
        size_t dbase = (size_t)row * D_MODEL + n * HDIM + q2;
        #pragma unroll
        for (int nt = 0; nt < 16; nt++) {
            uint32_t hi, lo;
            pack_split(O[nt][2 * h] * inv, O[nt][2 * h + 1] * inv, hi, lo);
            *reinterpret_cast<uint32_t*>(g_Ah + dbase + nt * 8) = hi;
            *reinterpret_cast<uint32_t*>(g_Al + dbase + nt * 8) = lo;
        }
    }
}

// ---------------- launch ----------------
extern "C" void kernel_launch(void* const* d_in, const int* in_sizes, int n_in,
                              void* d_out, int out_size) {
    const float* x      = (const float*)d_in[0];
    const int*   segpos = (const int*)d_in[1];
    const float* qw   = (const float*)d_in[3];
    const float* kvw  = (const float*)d_in[4];
    const float* outw = (const float*)d_in[5];
    float* out = (float*)d_out;

    __half *pAh, *pAl, *pBp, *pBo, *pQh, *pQl, *pKs;
    float* pQKV;
    cudaGetSymbolAddress((void**)&pAh, g_Ah);
    cudaGetSymbolAddress((void**)&pAl, g_Al);
    cudaGetSymbolAddress((void**)&pBp, g_Bp);
    cudaGetSymbolAddress((void**)&pBo, g_Bo);
    cudaGetSymbolAddress((void**)&pQh, g_Qh);
    cudaGetSymbolAddress((void**)&pQl, g_Ql2);
    cudaGetSymbolAddress((void**)&pKs, g_Ks);
    cudaGetSymbolAddress((void**)&pQKV, g_QKV);

    pack_convert<<<2048, 256>>>(x, qw, kvw, outw);

    const int GEMM_SMEM = 2 * STAGE2 * (int)sizeof(__half);  // 141312
    cudaFuncSetAttribute(gemm_fp16split, cudaFuncAttributeMaxDynamicSharedMemorySize, GEMM_SMEM);

    // fused QKV projection: (2048, 4096) @ (4096, 6144)
    gemm_fp16split<<<dim3(NPROJ / 256, T_SEQ / 128), 256, GEMM_SMEM>>>(pAh, pAl, pBp, pQKV,
                                                                       T_SEQ, NPROJ, D_MODEL);

    rope_split<<<(T_SEQ * NHEADS * 64 + 255) / 256, 256>>>(pQKV, NPROJ, 0, segpos, NHEADS,
                                                           0.08838834764831845f, pQh, pQl);
    rope_split<<<(T_SEQ * KVHEADS * 64 + 255) / 256, 256>>>(pQKV, NPROJ, 4096, segpos, KVHEADS,
                                                            1.0f, pKs, nullptr);
    v_split<<<512, 256>>>();

    const int ATTN_SMEM = 2 * STAGE2A * (int)sizeof(__half);  // 69632
    cudaFuncSetAttribute(attn_tc, cudaFuncAttributeMaxDynamicSharedMemorySize, ATTN_SMEM);
    attn_tc<<<dim3(NHEADS, T_SEQ / 128), 256, ATTN_SMEM>>>(segpos);

    // out projection: (2048, 4096) @ (4096, 4096)
    gemm_fp16split<<<dim3(D_MODEL / 256, T_SEQ / 128), 256, GEMM_SMEM>>>(pAh, pAl, pBo, out,
                                                                         T_SEQ, D_MODEL, D_MODEL);
}